// round 11
// baseline (speedup 1.0000x reference)
#include <cuda_runtime.h>
#include <cuda_fp16.h>
#include <cstdint>

// ---------------- problem constants ----------------
#define BN   2
#define SQn  2048
#define SKn  2048
#define Hn   16
#define HKVn 4
#define Dn   128
#define GQn  (Hn / HKVn)
#define TQ   128
#define TK   64
#define NT   128

#define SLOG2E  (0.08838834764831845f * 1.4426950408889634f)
#define SHIFT   5.0f

// ---------------- smem layout (bytes) ----------------
#define PADB     272
#define BUFSZ    34816            // K (17408) + V (17408)
#define OFF_V    17408
#define OFF_Q    (2 * BUFSZ)      // Q tile: 128 rows x 272B = 34816
#define SMEM_TOTAL (2 * BUFSZ + 34816)   // 104448 -> 2 CTAs/SM

__device__ int    g_len[BN];
__device__ float  g_vmean[BN * HKVn * Dn];
__device__ __half g_kvh[(size_t)BN * SKn * 2 * HKVn * Dn];   // 8MB fp16 KV

// ---------------- helpers ----------------
__device__ __forceinline__ uint32_t smem_u32(const void* p) {
    uint32_t a;
    asm("{ .reg .u64 t; cvta.to.shared.u64 t, %1; cvt.u32.u64 %0, t; }" : "=r"(a) : "l"(p));
    return a;
}
__device__ __forceinline__ void cp_async16(uint32_t dst, const void* src) {
    asm volatile("cp.async.cg.shared.global [%0], [%1], 16;" :: "r"(dst), "l"(src));
}
__device__ __forceinline__ void ldsm4(uint32_t& r0, uint32_t& r1, uint32_t& r2, uint32_t& r3, uint32_t a) {
    asm volatile("ldmatrix.sync.aligned.m8n8.x4.shared.b16 {%0,%1,%2,%3}, [%4];"
                 : "=r"(r0), "=r"(r1), "=r"(r2), "=r"(r3) : "r"(a));
}
__device__ __forceinline__ void ldsm4t(uint32_t& r0, uint32_t& r1, uint32_t& r2, uint32_t& r3, uint32_t a) {
    asm volatile("ldmatrix.sync.aligned.m8n8.x4.trans.shared.b16 {%0,%1,%2,%3}, [%4];"
                 : "=r"(r0), "=r"(r1), "=r"(r2), "=r"(r3) : "r"(a));
}
__device__ __forceinline__ void mma16816(float* c, uint32_t a0, uint32_t a1, uint32_t a2, uint32_t a3,
                                         uint32_t b0, uint32_t b1) {
    asm volatile("mma.sync.aligned.m16n8k16.row.col.f32.f16.f16.f32 "
                 "{%0,%1,%2,%3}, {%4,%5,%6,%7}, {%8,%9}, {%0,%1,%2,%3};"
                 : "+f"(c[0]), "+f"(c[1]), "+f"(c[2]), "+f"(c[3])
                 : "r"(a0), "r"(a1), "r"(a2), "r"(a3), "r"(b0), "r"(b1));
}
__device__ __forceinline__ float ex2f(float x) {
    float y; asm("ex2.approx.f32 %0, %1;" : "=f"(y) : "f"(x)); return y;
}
__device__ __forceinline__ uint32_t pkh(float a, float b) {
    __half2 t = __floats2half2_rn(a, b);
    return *reinterpret_cast<uint32_t*>(&t);
}

// ---------------- fused prep kernel: convert KV + lengths + vmean ----------------
#define CONV_BLKS 2048
__global__ void prep_kernel(const float* __restrict__ kv, const void* maskp) {
    const int bid = blockIdx.x;
    const int tid = threadIdx.x;

    if (bid < CONV_BLKS) {
        size_t e = (size_t)bid * 2048 + tid * 8;
        float4 v0 = *(const float4*)(kv + e);
        float4 v1 = *(const float4*)(kv + e + 4);
        uint4 hw = make_uint4(pkh(v0.x, v0.y), pkh(v0.z, v0.w),
                              pkh(v1.x, v1.y), pkh(v1.z, v1.w));
        *(uint4*)(&g_kvh[e]) = hw;
        return;
    }
    if (bid < CONV_BLKS + 2) {
        const unsigned char* mb = (const unsigned char*)maskp;
        int b = bid - CONV_BLKS;
        int mode;
        if (mb[0] == 1 && mb[1] == 1 && mb[2] == 1 && mb[3] == 1) mode = 0;      // bool
        else if (mb[0] == 1 && mb[1] == 0 && mb[2] == 0 && mb[3] == 0) mode = 1; // int32
        else mode = 2;                                                            // float32
        __shared__ int red[256];
        int cnt = 0;
        for (int s = tid; s < SKn; s += 256) {
            long idx = (long)b * SKn + s;
            bool nz;
            if (mode == 0)      nz = (mb[idx] != 0);
            else if (mode == 1) nz = (((const int*)maskp)[idx] != 0);
            else                nz = (((const float*)maskp)[idx] != 0.0f);
            cnt += nz ? 1 : 0;
        }
        red[tid] = cnt;
        __syncthreads();
        for (int off = 128; off > 0; off >>= 1) {
            if (tid < off) red[tid] += red[tid + off];
            __syncthreads();
        }
        if (tid == 0) g_len[b] = red[0];
        return;
    }
    {
        int idx = bid - (CONV_BLKS + 2);
        int b = idx >> 5, hk = (idx >> 3) & 3, dc = idx & 7;
        int dl = tid & 15, slice = tid >> 4;
        int d = dc * 16 + dl;
        float sum = 0.f;
        for (int s = slice; s < SKn; s += 16)
            sum += kv[((((size_t)b * SKn + s) * 2 + 1) * HKVn + hk) * Dn + d];
        __shared__ float red[256];
        red[tid] = sum;
        __syncthreads();
        for (int off = 8; off > 0; off >>= 1) {
            if (slice < off) red[slice * 16 + dl] += red[(slice + off) * 16 + dl];
            __syncthreads();
        }
        if (slice == 0) g_vmean[(b * HKVn + hk) * Dn + d] = red[dl] * (1.0f / SKn);
    }
}

// ---------------- main attention kernel ----------------
extern __shared__ char smem[];

__global__ void __launch_bounds__(NT, 2)
attn_kernel(const float* __restrict__ q, float* __restrict__ out) {
    // heavy-first flattened grid (512 items): bid 0 -> largest t0
    const int bid  = blockIdx.x;
    const int qrev = bid >> 5;                  // 0..15
    const int rest = bid & 31;
    const int h    = rest >> 1;
    const int b    = rest & 1;
    const int t0   = ((SQn / TQ - 1) - qrev) * TQ;

    const int hk  = h / GQn;
    const int len = g_len[b];
    const int tid = threadIdx.x;
    const int wid = tid >> 5, lane = tid & 31;
    const int g   = lane >> 2, tig = lane & 3;

    const uint32_t sb = smem_u32(smem);

    // per-warp 32 q-rows: [t0 + wid*32, +32)
    const int wrow = wid * 32;
    int clim[2][2];                            // [mt][lo/hi]
#pragma unroll
    for (int mt = 0; mt < 2; mt++) {
        clim[mt][0] = t0 + wrow + mt * 16 + g + len - SQn;
        clim[mt][1] = clim[mt][0] + 8;
    }
    const int wlim = t0 + wrow + 31 + len - SQn;

    const int lim = t0 + TQ - 1 + len - SQn;
    const int nt = (lim < 0) ? 0 : min(SKn / TK, lim / TK + 1);

    float oacc0[16][4], oacc1[16][4];
#pragma unroll
    for (int n = 0; n < 16; n++)
#pragma unroll
        for (int e = 0; e < 4; e++) { oacc0[n][e] = 0.f; oacc1[n][e] = 0.f; }
    float lsum[2][2] = {{0.f, 0.f}, {0.f, 0.f}};

    const __half* kbase = g_kvh + (((size_t)b * SKn) * 2 + 0) * HKVn * Dn + (size_t)hk * Dn;
    const __half* vbase = g_kvh + (((size_t)b * SKn) * 2 + 1) * HKVn * Dn + (size_t)hk * Dn;
    const size_t kvstr = (size_t)2 * HKVn * Dn;

    // ldmatrix bases
    const uint32_t kRowPart = ((lane >> 4) << 3) + (lane & 7);
    const uint32_t kKPart   = ((lane >> 3) & 1) << 4;
    const uint32_t baseK = sb + kRowPart * PADB + kKPart;
    const uint32_t vSPart = (lane & 7) + (((lane >> 3) & 1) << 3);
    const uint32_t vDPart = (lane >> 4) << 4;
    const uint32_t baseV = sb + OFF_V + vSPart * PADB + vDPart;
    // Q a-frag base: m0 rows0-7 k0-7 | m1 rows8-15 k0-7 | m2 rows0-7 k8-15 | m3 rows8-15 k8-15
    const uint32_t qRowPart = (((lane >> 3) & 1) << 3) + (lane & 7);
    const uint32_t qKPart   = (lane >> 4) << 4;
    const uint32_t baseQ = sb + OFF_Q + (wrow + qRowPart) * PADB + qKPart;

    if (nt > 0) {
        // ---- stage KV tile 0 into buf 0 ----
        {
#pragma unroll
            for (int p = 0; p < 16; p++) {
                int idx = tid + p * NT;
                int row = idx >> 4, ch = idx & 15;
                const __half* src = (row < 64) ? (kbase + (size_t)row * kvstr + ch * 8)
                                               : (vbase + (size_t)(row - 64) * kvstr + ch * 8);
                uint32_t dst = sb + ((row < 64) ? 0 : OFF_V) + (row & 63) * PADB + ch * 16;
                cp_async16(dst, src);
            }
            asm volatile("cp.async.commit_group;");
        }

        // ---- Q tile fp32->fp16 into smem (overlaps cp.async) ----
        {
            const float* qb = q + (((size_t)b * SQn + t0) * Hn + h) * Dn;
#pragma unroll
            for (int p = 0; p < 32; p++) {
                int idx = tid + p * NT;          // 0..4095 float4s
                int row = idx >> 5, c4 = idx & 31;
                float4 v = *(const float4*)(qb + (size_t)row * Hn * Dn + c4 * 4);
                *(uint2*)(smem + OFF_Q + row * PADB + c4 * 8) =
                    make_uint2(pkh(v.x, v.y), pkh(v.z, v.w));
            }
        }

        for (int it = 0; it < nt; it++) {
            const int s0 = it * TK;
            asm volatile("cp.async.wait_group 0;");
            // ONE barrier: KV tile it (and Q on it=0) visible to all warps, AND
            // all warps finished iter it-1 so buf[(it+1)&1] is free to restage.
            __syncthreads();

            // ---- stage tile it+1 into the freed buffer (consumed next iter) ----
            if (it + 1 < nt) {
                const __half* kb = kbase + (size_t)((it + 1) * TK) * kvstr;
                const __half* vb = vbase + (size_t)((it + 1) * TK) * kvstr;
                const uint32_t stb = sb + (((it + 1) & 1) ? BUFSZ : 0);
#pragma unroll
                for (int p = 0; p < 16; p++) {
                    int idx = tid + p * NT;
                    int row = idx >> 4, ch = idx & 15;
                    const __half* src = (row < 64) ? (kb + (size_t)row * kvstr + ch * 8)
                                                   : (vb + (size_t)(row - 64) * kvstr + ch * 8);
                    uint32_t dst = stb + ((row < 64) ? 0 : OFF_V) + (row & 63) * PADB + ch * 16;
                    cp_async16(dst, src);
                }
                asm volatile("cp.async.commit_group;");
            }

            if (s0 > wlim) continue;            // per-warp tile skip (warp-uniform)
            const uint32_t buf = (it & 1) ? BUFSZ : 0;

            // ---- S = Q K^T for both 16-row m-tiles; K frags read ONCE ----
            float sacc0[8][4], sacc1[8][4];
#pragma unroll
            for (int n = 0; n < 8; n++)
#pragma unroll
                for (int e = 0; e < 4; e++) { sacc0[n][e] = 0.f; sacc1[n][e] = 0.f; }

#pragma unroll
            for (int kc = 0; kc < 8; kc++) {
                uint32_t kf[16];
#pragma unroll
                for (int j = 0; j < 4; j++)
                    ldsm4(kf[4 * j], kf[4 * j + 1], kf[4 * j + 2], kf[4 * j + 3],
                          baseK + buf + j * (16 * PADB) + kc * 32);
                uint32_t a0, a1, a2, a3;
                ldsm4(a0, a1, a2, a3, baseQ + kc * 32);
#pragma unroll
                for (int j = 0; j < 4; j++) {
                    mma16816(sacc0[2 * j],     a0, a1, a2, a3, kf[4 * j],     kf[4 * j + 1]);
                    mma16816(sacc0[2 * j + 1], a0, a1, a2, a3, kf[4 * j + 2], kf[4 * j + 3]);
                }
                ldsm4(a0, a1, a2, a3, baseQ + 16 * PADB + kc * 32);
#pragma unroll
                for (int j = 0; j < 4; j++) {
                    mma16816(sacc1[2 * j],     a0, a1, a2, a3, kf[4 * j],     kf[4 * j + 1]);
                    mma16816(sacc1[2 * j + 1], a0, a1, a2, a3, kf[4 * j + 2], kf[4 * j + 3]);
                }
            }

            // ---- softmax both m-tiles: p' = 2^(s*log2e - SHIFT) ----
            uint32_t ph0[4][4], ph1[4][4];
#pragma unroll
            for (int mt = 0; mt < 2; mt++) {
                float (*sa)[4] = mt ? sacc1 : sacc0;
                uint32_t (*ph)[4] = mt ? ph1 : ph0;
#pragma unroll
                for (int n = 0; n < 8; n++) {
                    const int col = s0 + 8 * n + 2 * tig;
                    float p0 = ex2f(fmaf(sa[n][0], SLOG2E, -SHIFT));
                    float p1 = ex2f(fmaf(sa[n][1], SLOG2E, -SHIFT));
                    float p2 = ex2f(fmaf(sa[n][2], SLOG2E, -SHIFT));
                    float p3 = ex2f(fmaf(sa[n][3], SLOG2E, -SHIFT));
                    p0 = (col     <= clim[mt][0]) ? p0 : 0.f;
                    p1 = (col + 1 <= clim[mt][0]) ? p1 : 0.f;
                    p2 = (col     <= clim[mt][1]) ? p2 : 0.f;
                    p3 = (col + 1 <= clim[mt][1]) ? p3 : 0.f;
                    lsum[mt][0] += p0 + p1;
                    lsum[mt][1] += p2 + p3;
                    const int kc2 = n >> 1, hl = n & 1;
                    ph[kc2][0 + hl * 2] = pkh(p0, p1);
                    ph[kc2][1 + hl * 2] = pkh(p2, p3);
                }
            }

            // ---- O += P V for both m-tiles; V frags read ONCE ----
#pragma unroll
            for (int kc2 = 0; kc2 < 4; kc2++) {
#pragma unroll
                for (int j = 0; j < 8; j++) {
                    uint32_t v0, v1, v2, v3;
                    ldsm4t(v0, v1, v2, v3, baseV + buf + kc2 * (16 * PADB) + j * 32);
                    mma16816(oacc0[2 * j],     ph0[kc2][0], ph0[kc2][1], ph0[kc2][2], ph0[kc2][3], v0, v1);
                    mma16816(oacc0[2 * j + 1], ph0[kc2][0], ph0[kc2][1], ph0[kc2][2], ph0[kc2][3], v2, v3);
                    mma16816(oacc1[2 * j],     ph1[kc2][0], ph1[kc2][1], ph1[kc2][2], ph1[kc2][3], v0, v1);
                    mma16816(oacc1[2 * j + 1], ph1[kc2][0], ph1[kc2][1], ph1[kc2][2], ph1[kc2][3], v2, v3);
                }
            }
        }
    }

    // ---- epilogue ----
#pragma unroll
    for (int mt = 0; mt < 2; mt++) {
        lsum[mt][0] += __shfl_xor_sync(0xffffffffu, lsum[mt][0], 1);
        lsum[mt][0] += __shfl_xor_sync(0xffffffffu, lsum[mt][0], 2);
        lsum[mt][1] += __shfl_xor_sync(0xffffffffu, lsum[mt][1], 1);
        lsum[mt][1] += __shfl_xor_sync(0xffffffffu, lsum[mt][1], 2);
    }

    const float* vm = g_vmean + (b * HKVn + hk) * Dn;
#pragma unroll
    for (int mt = 0; mt < 2; mt++) {
        float (*oa)[4] = mt ? oacc1 : oacc0;
        const int r_lo = t0 + wrow + mt * 16 + g;
        const int r_hi = r_lo + 8;
        const bool mk_lo = (r_lo + len - SQn) < 0;
        const bool mk_hi = (r_hi + len - SQn) < 0;
        const float inv_lo = mk_lo ? 0.f : 1.0f / lsum[mt][0];
        const float inv_hi = mk_hi ? 0.f : 1.0f / lsum[mt][1];
        float* out_lo = out + (((size_t)b * SQn + r_lo) * Hn + h) * Dn;
        float* out_hi = out + (((size_t)b * SQn + r_hi) * Hn + h) * Dn;
#pragma unroll
        for (int nn = 0; nn < 16; nn++) {
            const int d = 8 * nn + 2 * tig;
            float2 wlo, whi;
            if (mk_lo) { wlo.x = vm[d]; wlo.y = vm[d + 1]; }
            else       { wlo.x = oa[nn][0] * inv_lo; wlo.y = oa[nn][1] * inv_lo; }
            if (mk_hi) { whi.x = vm[d]; whi.y = vm[d + 1]; }
            else       { whi.x = oa[nn][2] * inv_hi; whi.y = oa[nn][3] * inv_hi; }
            *(float2*)(out_lo + d) = wlo;
            *(float2*)(out_hi + d) = whi;
        }
    }
}

// ---------------- launcher ----------------
extern "C" void kernel_launch(void* const* d_in, const int* in_sizes, int n_in,
                              void* d_out, int out_size) {
    const float* q    = (const float*)d_in[0];
    const float* kv   = (const float*)d_in[1];
    const void*  mask = d_in[2];
    float* out = (float*)d_out;

    prep_kernel<<<CONV_BLKS + 2 + 64, 256>>>(kv, mask);

    cudaFuncSetAttribute(attn_kernel, cudaFuncAttributeMaxDynamicSharedMemorySize, SMEM_TOTAL);
    attn_kernel<<<(SQn / TQ) * Hn * BN, NT, SMEM_TOTAL>>>(q, out);
}